// round 16
// baseline (speedup 1.0000x reference)
#include <cuda_runtime.h>
#include <cuda_fp16.h>
#include <cstdint>

// ============================================================================
// GCN layer on GB300 (sm_103 base target):
//   fused : blocks 0..127: 4x 64x64 GEMM tiles each -> Qt=(H@W)^T fp32
//           blocks 128..8319: d = rowsum(A)^-1/2, Ah = fp16(A)
//           (few fat GEMM blocks -> no DRAM-starved GEMM window)
//   scaleP: Pth[f][k] = fp16( d[k] * Qt[f][k] )
//   spmm  : out = relu( d_m * sum_k Ah[m,k]*Pth[n,k] ), 148 CTAs,
//           KT=128 / NS=3 (halved per-iter pipeline overhead)
// ============================================================================

#define NROWS 8192
#define FDIM  256

__device__ float g_d[NROWS];
__device__ __align__(16) __half g_Ah[(size_t)NROWS * NROWS];   // fp16 A, 128MB
__device__ __align__(16) float  g_Qt[FDIM * NROWS];            // (HW)^T fp32, 8MB
__device__ __align__(16) __half g_Pth[FDIM * NROWS];           // scaled fp16, 4MB

// ---------------- helpers ----------------
__device__ __forceinline__ uint32_t smem_u32(const void* p) {
    uint32_t a;
    asm("{ .reg .u64 t; cvta.to.shared.u64 t, %1; cvt.u32.u64 %0, t; }" : "=r"(a) : "l"(p));
    return a;
}
__device__ __forceinline__ uint64_t pack2dup(float v) {
    uint64_t r; asm("mov.b64 %0, {%1, %2};" : "=l"(r) : "f"(v), "f"(v)); return r;
}
__device__ __forceinline__ uint64_t fma2(uint64_t a, uint64_t b, uint64_t c) {
    uint64_t d; asm("fma.rn.f32x2 %0, %1, %2, %3;" : "=l"(d) : "l"(a), "l"(b), "l"(c)); return d;
}
__device__ __forceinline__ void unpack2(uint64_t v, float& lo, float& hi) {
    asm("mov.b64 {%0, %1}, %2;" : "=f"(lo), "=f"(hi) : "l"(v));
}

#define CP_ASYNC16(sdst, gsrc) \
    asm volatile("cp.async.cg.shared.global [%0], [%1], 16;" :: "r"(sdst), "l"(gsrc) : "memory")
#define CP_COMMIT() asm volatile("cp.async.commit_group;" ::: "memory")
#define CP_WAIT1()  asm volatile("cp.async.wait_group 1;" ::: "memory")

__device__ __forceinline__ uint32_t lds32(uint32_t p) {
    uint32_t v; asm volatile("ld.shared.b32 %0, [%1];" : "=r"(v) : "r"(p)); return v;
}

// ---------------------------------------------------------------------------
// Fused phase 1: 128 fat GEMM blocks (4 tiles each) + 8192 rowsum blocks.
// ---------------------------------------------------------------------------
#define GEMM_BLOCKS 128
#define BKS 16

__global__ __launch_bounds__(256, 5) void fused_pre(const float* __restrict__ A,
                                                    const float* __restrict__ H,
                                                    const float* __restrict__ W,
                                                    float* __restrict__ d,
                                                    __half* __restrict__ Ah,
                                                    float* __restrict__ Qt) {
    __shared__ float As[BKS][64];
    __shared__ float Bs[BKS][64];
    __shared__ float red[8];

    const int tid = threadIdx.x;

    if (blockIdx.x >= GEMM_BLOCKS) {
        // ---------------- rowsum + fp16 convert ----------------
        const int row = blockIdx.x - GEMM_BLOCKS;
        const float4* Ar = (const float4*)(A + (size_t)row * NROWS);
        uint2* Hr = (uint2*)(Ah + (size_t)row * NROWS);
        float s = 0.f;
        #pragma unroll
        for (int i = 0; i < 8; i++) {
            const int idx = tid + 256 * i;
            float4 v = Ar[idx];
            s += (v.x + v.y) + (v.z + v.w);
            __half2 h01 = __floats2half2_rn(v.x, v.y);
            __half2 h23 = __floats2half2_rn(v.z, v.w);
            uint2 u;
            u.x = *(uint32_t*)&h01;
            u.y = *(uint32_t*)&h23;
            Hr[idx] = u;
        }
        #pragma unroll
        for (int o = 16; o; o >>= 1) s += __shfl_xor_sync(0xffffffffu, s, o);
        if ((tid & 31) == 0) red[tid >> 5] = s;
        __syncthreads();
        if (tid < 8) {
            s = red[tid];
            #pragma unroll
            for (int o = 4; o; o >>= 1) s += __shfl_xor_sync(0xffu, s, o);
            if (tid == 0) d[row] = rsqrtf(s);
        }
        return;
    }

    // ------------- GEMM: 4 consecutive 64x64 tiles (same bm, 4 bn) --------
    const int tx = tid & 15;
    const int ty = tid >> 4;
    const int bm = (int)blockIdx.x * 64;      // 128 blocks x 64 rows = 8192
    const int arow = tid >> 2;
    const int acol = (tid & 3) << 2;
    const float* Ap = H + (size_t)(bm + arow) * FDIM + acol;
    const int brow = tid >> 4;
    const int bcol = (tid & 15) << 2;

    for (int t = 0; t < 4; t++) {
        const int bn = t * 64;
        const float* Bp = W + (size_t)brow * FDIM + bn + bcol;

        uint64_t acc[2][4];
        #pragma unroll
        for (int i = 0; i < 2; i++)
            #pragma unroll
            for (int j = 0; j < 4; j++) acc[i][j] = 0ull;

        float4 pa = *(const float4*)(Ap);
        float4 pb = *(const float4*)(Bp);

        for (int kt = 0; kt < FDIM; kt += BKS) {
            As[acol + 0][arow] = pa.x; As[acol + 1][arow] = pa.y;
            As[acol + 2][arow] = pa.z; As[acol + 3][arow] = pa.w;
            *(float4*)&Bs[brow][bcol] = pb;
            __syncthreads();

            const int ktn = kt + BKS;
            if (ktn < FDIM) {
                pa = *(const float4*)(Ap + ktn);
                pb = *(const float4*)(Bp + (size_t)ktn * FDIM);
            }

            #pragma unroll
            for (int k = 0; k < BKS; k++) {
                const ulonglong2 av2 = *(const ulonglong2*)&As[k][ty * 4];
                const uint64_t av[2] = {av2.x, av2.y};
                const float4 bv = *(const float4*)&Bs[k][tx * 4];
                uint64_t bb[4];
                bb[0] = pack2dup(bv.x); bb[1] = pack2dup(bv.y);
                bb[2] = pack2dup(bv.z); bb[3] = pack2dup(bv.w);
                #pragma unroll
                for (int i = 0; i < 2; i++)
                    #pragma unroll
                    for (int j = 0; j < 4; j++)
                        acc[i][j] = fma2(av[i], bb[j], acc[i][j]);
            }
            __syncthreads();
        }

        const int m0 = bm + ty * 4;
        #pragma unroll
        for (int j = 0; j < 4; j++) {
            const int col = bn + tx * 4 + j;
            float v[4];
            unpack2(acc[0][j], v[0], v[1]);
            unpack2(acc[1][j], v[2], v[3]);
            *(float4*)(Qt + (size_t)col * NROWS + m0) = make_float4(v[0], v[1], v[2], v[3]);
        }
    }
}

// ---------------------------------------------------------------------------
// scaleP: Pth[f][k] = fp16( d[k] * Qt[f][k] )
// ---------------------------------------------------------------------------
__global__ __launch_bounds__(256) void scaleP(const float* __restrict__ Qt,
                                              const float* __restrict__ dvec,
                                              __half* __restrict__ Pth) {
    const size_t base = ((size_t)blockIdx.x * 256 + threadIdx.x) * 8;
    const size_t k = base & (NROWS - 1);
    float4 q0 = *(const float4*)(Qt + base);
    float4 q1 = *(const float4*)(Qt + base + 4);
    float4 d0 = *(const float4*)(dvec + k);
    float4 d1 = *(const float4*)(dvec + k + 4);
    __half2 h0 = __floats2half2_rn(q0.x * d0.x, q0.y * d0.y);
    __half2 h1 = __floats2half2_rn(q0.z * d0.z, q0.w * d0.w);
    __half2 h2 = __floats2half2_rn(q1.x * d1.x, q1.y * d1.y);
    __half2 h3 = __floats2half2_rn(q1.z * d1.z, q1.w * d1.w);
    uint4 u;
    u.x = *(uint32_t*)&h0; u.y = *(uint32_t*)&h1;
    u.z = *(uint32_t*)&h2; u.w = *(uint32_t*)&h3;
    *(uint4*)(Pth + base) = u;
}

// ---------------------------------------------------------------------------
// spmm: out = relu( d_m * sum_k Ah[m,k] * Pth[n,k] )
// 148 CTAs (68x112-row + 6x96-row M-tiles, x2 N-halves).
// KT=128 halves/iter, NS=3 ring (195.8KB). Fragment path unchanged (ROWB=272,
// bank-clean: 68*r mod 32 = 4r). 64 iterations -> half the barrier overhead.
// ---------------------------------------------------------------------------
#define NS 3
#define KT 128
#define NITER (NROWS / KT)            // 64
#define ROWB 272                      // 256B data + 16B pad
#define MMAX 112
#define TILE_A (MMAX * ROWB)          // 30464
#define TILE_B (128 * ROWB)           // 34816
#define STG_B (TILE_A + TILE_B)       // 65280
#define SMEM_BIG (NS * STG_B)         // 195840

__global__ __launch_bounds__(256, 1) void spmm_mma(const __half* __restrict__ Ah,
                                                   const __half* __restrict__ Pth,
                                                   const float* __restrict__ dvec,
                                                   float* __restrict__ out) {
    extern __shared__ char smem[];
    const uint32_t sb = smem_u32(smem);
    const int tid = threadIdx.x;
    const int lane = tid & 31;
    const int wid = tid >> 5;
    const int warp_m = wid >> 2;
    const int warp_n = wid & 3;
    const int by = (int)blockIdx.y;
    const int bn = (int)blockIdx.x * 128;

    int bm, mrows;
    if (by < 68) { bm = by * 112; mrows = 112; }
    else         { bm = 7616 + (by - 68) * 96; mrows = 96; }
    const int mt_cnt = warp_m == 0 ? 4 : ((mrows - 64) >> 4);
    const bool m112 = (mrows == 112);

    // loader mapping: r = r0 + 16*i (r0 = tid>>4), c = tid&15 (16B chunks)
    const int r0 = tid >> 4;
    const int c16 = (tid & 15) * 16;             // byte offset within row
    const char* aSrc = (const char*)(Ah + (size_t)(bm + r0) * NROWS) + c16;
    const char* bSrc = (const char*)(Pth + (size_t)(bn + r0) * NROWS) + c16;
    const uint32_t aDst = (uint32_t)(r0 * ROWB + c16);
    const uint32_t bDst = (uint32_t)(TILE_A + r0 * ROWB + c16);
    const size_t SRC_STRIDE = (size_t)16 * NROWS * 2;   // 16 rows, bytes
    const uint32_t DST_STRIDE = 16 * ROWB;

    auto load_stage = [&](int s, int it) {
        const uint32_t base = sb + s * STG_B;
        const size_t koff = (size_t)it * (KT * 2);
        #pragma unroll
        for (int i = 0; i < 7; i++)             // A: 112 rows max
            if (i < 6 || m112)
                CP_ASYNC16(base + aDst + i * DST_STRIDE, aSrc + i * SRC_STRIDE + koff);
        #pragma unroll
        for (int i = 0; i < 8; i++)             // B: 128 rows
            CP_ASYNC16(base + bDst + i * DST_STRIDE, bSrc + i * SRC_STRIDE + koff);
    };

    float acc[4][4][4];
    #pragma unroll
    for (int mt = 0; mt < 4; mt++)
        #pragma unroll
        for (int nt = 0; nt < 4; nt++)
            #pragma unroll
            for (int q = 0; q < 4; q++) acc[mt][nt][q] = 0.f;

    // prologue: stages 0, 1
    load_stage(0, 0); CP_COMMIT();
    load_stage(1, 1); CP_COMMIT();

    const uint32_t a_lane_off = (uint32_t)((warp_m * 64 + (lane >> 2)) * ROWB + (lane & 3) * 4);
    const uint32_t b_lane_off = (uint32_t)(TILE_A + (warp_n * 32 + (lane >> 2)) * ROWB + (lane & 3) * 4);

    for (int it = 0; it < NITER; it++) {
        CP_WAIT1();                 // stage 'it' resident (one newer in flight)
        __syncthreads();            // all warps done with stage it-1

        const int j = it + 2;
        if (j < NITER) load_stage(j % NS, j);   // overwrites stage (it-1)%NS
        CP_COMMIT();                // empty groups in tail keep numbering exact

        const uint32_t stage = sb + (it % NS) * STG_B;
        #pragma unroll
        for (int kc = 0; kc < 8; kc++) {        // 8 x 16 halves = 128
            const uint32_t kb = (uint32_t)(kc * 32);
            uint32_t a[4][4];
            #pragma unroll
            for (int mt = 0; mt < 4; mt++) {
                if (mt < mt_cnt) {
                    const uint32_t p = stage + a_lane_off + mt * (16 * ROWB) + kb;
                    a[mt][0] = lds32(p);
                    a[mt][1] = lds32(p + 8 * ROWB);
                    a[mt][2] = lds32(p + 16);
                    a[mt][3] = lds32(p + 8 * ROWB + 16);
                }
            }
            uint32_t b[4][2];
            #pragma unroll
            for (int nt = 0; nt < 4; nt++) {
                const uint32_t p = stage + b_lane_off + nt * (8 * ROWB) + kb;
                b[nt][0] = lds32(p);
                b[nt][1] = lds32(p + 16);
            }
            #pragma unroll
            for (int mt = 0; mt < 4; mt++) {
                if (mt < mt_cnt) {
                    #pragma unroll
                    for (int nt = 0; nt < 4; nt++)
                        asm volatile(
                            "mma.sync.aligned.m16n8k16.row.col.f32.f16.f16.f32 "
                            "{%0,%1,%2,%3}, {%4,%5,%6,%7}, {%8,%9}, {%0,%1,%2,%3};"
                            : "+f"(acc[mt][nt][0]), "+f"(acc[mt][nt][1]),
                              "+f"(acc[mt][nt][2]), "+f"(acc[mt][nt][3])
                            : "r"(a[mt][0]), "r"(a[mt][1]), "r"(a[mt][2]), "r"(a[mt][3]),
                              "r"(b[nt][0]), "r"(b[nt][1]));
                }
            }
        }
    }

    // epilogue: scale by d[row], relu, float2 stores
    #pragma unroll
    for (int mt = 0; mt < 4; mt++) {
        if (mt < mt_cnt) {
            const int r0e = bm + warp_m * 64 + mt * 16 + (lane >> 2);
            const float s0 = dvec[r0e];
            const float s1 = dvec[r0e + 8];
            #pragma unroll
            for (int nt = 0; nt < 4; nt++) {
                const int col = bn + warp_n * 32 + nt * 8 + (lane & 3) * 2;
                float2 v0, v1;
                v0.x = fmaxf(s0 * acc[mt][nt][0], 0.f);
                v0.y = fmaxf(s0 * acc[mt][nt][1], 0.f);
                v1.x = fmaxf(s1 * acc[mt][nt][2], 0.f);
                v1.y = fmaxf(s1 * acc[mt][nt][3], 0.f);
                *(float2*)(out + (size_t)r0e * FDIM + col)       = v0;
                *(float2*)(out + (size_t)(r0e + 8) * FDIM + col) = v1;
            }
        }
    }
}

// ---------------------------------------------------------------------------
extern "C" void kernel_launch(void* const* d_in, const int* in_sizes, int n_in,
                              void* d_out, int out_size) {
    const float* H = nullptr;
    const float* A = nullptr;
    const float* W = nullptr;
    for (int i = 0; i < n_in; i++) {
        if (in_sizes[i] == NROWS * NROWS) A = (const float*)d_in[i];
        else if (in_sizes[i] == FDIM * FDIM) W = (const float*)d_in[i];
        else if (in_sizes[i] == NROWS * FDIM) H = (const float*)d_in[i];
    }
    float* out = (float*)d_out;

    float* dptr = nullptr;
    __half* Ahp = nullptr;
    float* Qtp = nullptr;
    __half* Ptp = nullptr;
    cudaGetSymbolAddress((void**)&dptr, g_d);
    cudaGetSymbolAddress((void**)&Ahp, g_Ah);
    cudaGetSymbolAddress((void**)&Qtp, g_Qt);
    cudaGetSymbolAddress((void**)&Ptp, g_Pth);

    cudaFuncSetAttribute(spmm_mma, cudaFuncAttributeMaxDynamicSharedMemorySize, SMEM_BIG);

    // 1) fused: Qt = (H@W)^T fp32 (128 fat blocks) || d, Ah = fp16(A)
    fused_pre<<<GEMM_BLOCKS + NROWS, 256>>>(A, H, W, dptr, Ahp, Qtp);

    // 2) Pth = fp16(d[k] * Qt)
    scaleP<<<(FDIM * NROWS) / (256 * 8), 256>>>(Qtp, dptr, Ptp);

    // 3) out = relu(d_m * (Ah @ P)) -- 148 CTAs, KT=128/NS=3
    dim3 gridB(2, 74);
    spmm_mma<<<gridB, 256, SMEM_BIG>>>(Ahp, Ptp, dptr, out);
}

// round 17
// speedup vs baseline: 1.2262x; 1.2262x over previous
#include <cuda_runtime.h>
#include <cuda_fp16.h>
#include <cstdint>

// ============================================================================
// GCN layer on GB300 (sm_103 base target) -- measured-best components:
//   fused : blocks 0..511 (front-loaded, thin): Qt=(H@W)^T fp32 64x64 tiles
//           blocks 512..8703: d = rowsum(A)^-1/2, Ah = fp16(A)     [71.0us]
//   scaleP: Pth[f][k] = fp16( d[k] * Qt[f][k] )                    [~3us]
//   spmm  : out = relu( d_m * sum_k Ah[m,k]*Pth[n,k] ), 148 CTAs,
//           KT=128 / NS=3 (halved per-iter overhead)               [~120us]
// ============================================================================

#define NROWS 8192
#define FDIM  256

__device__ float g_d[NROWS];
__device__ __align__(16) __half g_Ah[(size_t)NROWS * NROWS];   // fp16 A, 128MB
__device__ __align__(16) float  g_Qt[FDIM * NROWS];            // (HW)^T fp32, 8MB
__device__ __align__(16) __half g_Pth[FDIM * NROWS];           // scaled fp16, 4MB

// ---------------- helpers ----------------
__device__ __forceinline__ uint32_t smem_u32(const void* p) {
    uint32_t a;
    asm("{ .reg .u64 t; cvta.to.shared.u64 t, %1; cvt.u32.u64 %0, t; }" : "=r"(a) : "l"(p));
    return a;
}
__device__ __forceinline__ uint64_t pack2dup(float v) {
    uint64_t r; asm("mov.b64 %0, {%1, %2};" : "=l"(r) : "f"(v), "f"(v)); return r;
}
__device__ __forceinline__ uint64_t fma2(uint64_t a, uint64_t b, uint64_t c) {
    uint64_t d; asm("fma.rn.f32x2 %0, %1, %2, %3;" : "=l"(d) : "l"(a), "l"(b), "l"(c)); return d;
}
__device__ __forceinline__ void unpack2(uint64_t v, float& lo, float& hi) {
    asm("mov.b64 {%0, %1}, %2;" : "=f"(lo), "=f"(hi) : "l"(v));
}

#define CP_ASYNC16(sdst, gsrc) \
    asm volatile("cp.async.cg.shared.global [%0], [%1], 16;" :: "r"(sdst), "l"(gsrc) : "memory")
#define CP_COMMIT() asm volatile("cp.async.commit_group;" ::: "memory")
#define CP_WAIT1()  asm volatile("cp.async.wait_group 1;" ::: "memory")

__device__ __forceinline__ uint32_t lds32(uint32_t p) {
    uint32_t v; asm volatile("ld.shared.b32 %0, [%1];" : "=r"(v) : "r"(p)); return v;
}

// ---------------------------------------------------------------------------
// Fused phase 1 (R14-proven, 71.0us): 512 thin GEMM blocks first, then rowsum.
// ---------------------------------------------------------------------------
#define GEMM_BLOCKS 512
#define BKS 16

__global__ __launch_bounds__(256, 5) void fused_pre(const float* __restrict__ A,
                                                    const float* __restrict__ H,
                                                    const float* __restrict__ W,
                                                    float* __restrict__ d,
                                                    __half* __restrict__ Ah,
                                                    float* __restrict__ Qt) {
    __shared__ float As[BKS][64];
    __shared__ float Bs[BKS][64];
    __shared__ float red[8];

    const int tid = threadIdx.x;

    if (blockIdx.x >= GEMM_BLOCKS) {
        // ---------------- rowsum + fp16 convert ----------------
        const int row = blockIdx.x - GEMM_BLOCKS;
        const float4* Ar = (const float4*)(A + (size_t)row * NROWS);
        uint2* Hr = (uint2*)(Ah + (size_t)row * NROWS);
        float s = 0.f;
        #pragma unroll
        for (int i = 0; i < 8; i++) {
            const int idx = tid + 256 * i;
            float4 v = Ar[idx];
            s += (v.x + v.y) + (v.z + v.w);
            __half2 h01 = __floats2half2_rn(v.x, v.y);
            __half2 h23 = __floats2half2_rn(v.z, v.w);
            uint2 u;
            u.x = *(uint32_t*)&h01;
            u.y = *(uint32_t*)&h23;
            Hr[idx] = u;
        }
        #pragma unroll
        for (int o = 16; o; o >>= 1) s += __shfl_xor_sync(0xffffffffu, s, o);
        if ((tid & 31) == 0) red[tid >> 5] = s;
        __syncthreads();
        if (tid < 8) {
            s = red[tid];
            #pragma unroll
            for (int o = 4; o; o >>= 1) s += __shfl_xor_sync(0xffu, s, o);
            if (tid == 0) d[row] = rsqrtf(s);
        }
        return;
    }

    // ---------------- thin GEMM: one 64x64 tile ----------------
    const int gid = (int)blockIdx.x;
    const int tx = tid & 15;
    const int ty = tid >> 4;
    const int bm = (gid >> 2) * 64;
    const int bn = (gid & 3) * 64;

    const int arow = tid >> 2;
    const int acol = (tid & 3) << 2;
    const float* Ap = H + (size_t)(bm + arow) * FDIM + acol;
    const int brow = tid >> 4;
    const int bcol = (tid & 15) << 2;
    const float* Bp = W + (size_t)brow * FDIM + bn + bcol;

    uint64_t acc[2][4];
    #pragma unroll
    for (int i = 0; i < 2; i++)
        #pragma unroll
        for (int j = 0; j < 4; j++) acc[i][j] = 0ull;

    float4 pa = *(const float4*)(Ap);
    float4 pb = *(const float4*)(Bp);

    for (int kt = 0; kt < FDIM; kt += BKS) {
        As[acol + 0][arow] = pa.x; As[acol + 1][arow] = pa.y;
        As[acol + 2][arow] = pa.z; As[acol + 3][arow] = pa.w;
        *(float4*)&Bs[brow][bcol] = pb;
        __syncthreads();

        const int ktn = kt + BKS;
        if (ktn < FDIM) {
            pa = *(const float4*)(Ap + ktn);
            pb = *(const float4*)(Bp + (size_t)ktn * FDIM);
        }

        #pragma unroll
        for (int k = 0; k < BKS; k++) {
            const ulonglong2 av2 = *(const ulonglong2*)&As[k][ty * 4];
            const uint64_t av[2] = {av2.x, av2.y};
            const float4 bv = *(const float4*)&Bs[k][tx * 4];
            uint64_t bb[4];
            bb[0] = pack2dup(bv.x); bb[1] = pack2dup(bv.y);
            bb[2] = pack2dup(bv.z); bb[3] = pack2dup(bv.w);
            #pragma unroll
            for (int i = 0; i < 2; i++)
                #pragma unroll
                for (int j = 0; j < 4; j++)
                    acc[i][j] = fma2(av[i], bb[j], acc[i][j]);
        }
        __syncthreads();
    }

    const int m0 = bm + ty * 4;
    #pragma unroll
    for (int j = 0; j < 4; j++) {
        const int col = bn + tx * 4 + j;
        float v[4];
        unpack2(acc[0][j], v[0], v[1]);
        unpack2(acc[1][j], v[2], v[3]);
        *(float4*)(Qt + (size_t)col * NROWS + m0) = make_float4(v[0], v[1], v[2], v[3]);
    }
}

// ---------------------------------------------------------------------------
// scaleP: Pth[f][k] = fp16( d[k] * Qt[f][k] )
// ---------------------------------------------------------------------------
__global__ __launch_bounds__(256) void scaleP(const float* __restrict__ Qt,
                                              const float* __restrict__ dvec,
                                              __half* __restrict__ Pth) {
    const size_t base = ((size_t)blockIdx.x * 256 + threadIdx.x) * 8;
    const size_t k = base & (NROWS - 1);
    float4 q0 = *(const float4*)(Qt + base);
    float4 q1 = *(const float4*)(Qt + base + 4);
    float4 d0 = *(const float4*)(dvec + k);
    float4 d1 = *(const float4*)(dvec + k + 4);
    __half2 h0 = __floats2half2_rn(q0.x * d0.x, q0.y * d0.y);
    __half2 h1 = __floats2half2_rn(q0.z * d0.z, q0.w * d0.w);
    __half2 h2 = __floats2half2_rn(q1.x * d1.x, q1.y * d1.y);
    __half2 h3 = __floats2half2_rn(q1.z * d1.z, q1.w * d1.w);
    uint4 u;
    u.x = *(uint32_t*)&h0; u.y = *(uint32_t*)&h1;
    u.z = *(uint32_t*)&h2; u.w = *(uint32_t*)&h3;
    *(uint4*)(Pth + base) = u;
}

// ---------------------------------------------------------------------------
// spmm (R16 inner config): out = relu( d_m * sum_k Ah[m,k] * Pth[n,k] )
// 148 CTAs (68x112 + 6x96 M-tiles, x2 N-halves). KT=128, NS=3 (195.8KB).
// ROWB=272 keeps the lds32 fragment path bank-clean.
// ---------------------------------------------------------------------------
#define NS 3
#define KT 128
#define NITER (NROWS / KT)            // 64
#define ROWB 272                      // 256B data + 16B pad
#define MMAX 112
#define TILE_A (MMAX * ROWB)          // 30464
#define TILE_B (128 * ROWB)           // 34816
#define STG_B (TILE_A + TILE_B)       // 65280
#define SMEM_BIG (NS * STG_B)         // 195840

__global__ __launch_bounds__(256, 1) void spmm_mma(const __half* __restrict__ Ah,
                                                   const __half* __restrict__ Pth,
                                                   const float* __restrict__ dvec,
                                                   float* __restrict__ out) {
    extern __shared__ char smem[];
    const uint32_t sb = smem_u32(smem);
    const int tid = threadIdx.x;
    const int lane = tid & 31;
    const int wid = tid >> 5;
    const int warp_m = wid >> 2;
    const int warp_n = wid & 3;
    const int by = (int)blockIdx.y;
    const int bn = (int)blockIdx.x * 128;

    int bm, mrows;
    if (by < 68) { bm = by * 112; mrows = 112; }
    else         { bm = 7616 + (by - 68) * 96; mrows = 96; }
    const int mt_cnt = warp_m == 0 ? 4 : ((mrows - 64) >> 4);
    const bool m112 = (mrows == 112);

    const int r0 = tid >> 4;
    const int c16 = (tid & 15) * 16;
    const char* aSrc = (const char*)(Ah + (size_t)(bm + r0) * NROWS) + c16;
    const char* bSrc = (const char*)(Pth + (size_t)(bn + r0) * NROWS) + c16;
    const uint32_t aDst = (uint32_t)(r0 * ROWB + c16);
    const uint32_t bDst = (uint32_t)(TILE_A + r0 * ROWB + c16);
    const size_t SRC_STRIDE = (size_t)16 * NROWS * 2;
    const uint32_t DST_STRIDE = 16 * ROWB;

    auto load_stage = [&](int s, int it) {
        const uint32_t base = sb + s * STG_B;
        const size_t koff = (size_t)it * (KT * 2);
        #pragma unroll
        for (int i = 0; i < 7; i++)
            if (i < 6 || m112)
                CP_ASYNC16(base + aDst + i * DST_STRIDE, aSrc + i * SRC_STRIDE + koff);
        #pragma unroll
        for (int i = 0; i < 8; i++)
            CP_ASYNC16(base + bDst + i * DST_STRIDE, bSrc + i * SRC_STRIDE + koff);
    };

    float acc[4][4][4];
    #pragma unroll
    for (int mt = 0; mt < 4; mt++)
        #pragma unroll
        for (int nt = 0; nt < 4; nt++)
            #pragma unroll
            for (int q = 0; q < 4; q++) acc[mt][nt][q] = 0.f;

    load_stage(0, 0); CP_COMMIT();
    load_stage(1, 1); CP_COMMIT();

    const uint32_t a_lane_off = (uint32_t)((warp_m * 64 + (lane >> 2)) * ROWB + (lane & 3) * 4);
    const uint32_t b_lane_off = (uint32_t)(TILE_A + (warp_n * 32 + (lane >> 2)) * ROWB + (lane & 3) * 4);

    for (int it = 0; it < NITER; it++) {
        CP_WAIT1();
        __syncthreads();

        const int j = it + 2;
        if (j < NITER) load_stage(j % NS, j);
        CP_COMMIT();

        const uint32_t stage = sb + (it % NS) * STG_B;
        #pragma unroll
        for (int kc = 0; kc < 8; kc++) {
            const uint32_t kb = (uint32_t)(kc * 32);
            uint32_t a[4][4];
            #pragma unroll
            for (int mt = 0; mt < 4; mt++) {
                if (mt < mt_cnt) {
                    const uint32_t p = stage + a_lane_off + mt * (16 * ROWB) + kb;
                    a[mt][0] = lds32(p);
                    a[mt][1] = lds32(p + 8 * ROWB);
                    a[mt][2] = lds32(p + 16);
                    a[mt][3] = lds32(p + 8 * ROWB + 16);
                }
            }
            uint32_t b[4][2];
            #pragma unroll
            for (int nt = 0; nt < 4; nt++) {
                const uint32_t p = stage + b_lane_off + nt * (8 * ROWB) + kb;
                b[nt][0] = lds32(p);
                b[nt][1] = lds32(p + 16);
            }
            #pragma unroll
            for (int mt = 0; mt < 4; mt++) {
                if (mt < mt_cnt) {
                    #pragma unroll
                    for (int nt = 0; nt < 4; nt++)
                        asm volatile(
                            "mma.sync.aligned.m16n8k16.row.col.f32.f16.f16.f32 "
                            "{%0,%1,%2,%3}, {%4,%5,%6,%7}, {%8,%9}, {%0,%1,%2,%3};"
                            : "+f"(acc[mt][nt][0]), "+f"(acc[mt][nt][1]),
                              "+f"(acc[mt][nt][2]), "+f"(acc[mt][nt][3])
                            : "r"(a[mt][0]), "r"(a[mt][1]), "r"(a[mt][2]), "r"(a[mt][3]),
                              "r"(b[nt][0]), "r"(b[nt][1]));
                }
            }
        }
    }

    #pragma unroll
    for (int mt = 0; mt < 4; mt++) {
        if (mt < mt_cnt) {
            const int r0e = bm + warp_m * 64 + mt * 16 + (lane >> 2);
            const float s0 = dvec[r0e];
            const float s1 = dvec[r0e + 8];
            #pragma unroll
            for (int nt = 0; nt < 4; nt++) {
                const int col = bn + warp_n * 32 + nt * 8 + (lane & 3) * 2;
                float2 v0, v1;
                v0.x = fmaxf(s0 * acc[mt][nt][0], 0.f);
                v0.y = fmaxf(s0 * acc[mt][nt][1], 0.f);
                v1.x = fmaxf(s1 * acc[mt][nt][2], 0.f);
                v1.y = fmaxf(s1 * acc[mt][nt][3], 0.f);
                *(float2*)(out + (size_t)r0e * FDIM + col)       = v0;
                *(float2*)(out + (size_t)(r0e + 8) * FDIM + col) = v1;
            }
        }
    }
}

// ---------------------------------------------------------------------------
extern "C" void kernel_launch(void* const* d_in, const int* in_sizes, int n_in,
                              void* d_out, int out_size) {
    const float* H = nullptr;
    const float* A = nullptr;
    const float* W = nullptr;
    for (int i = 0; i < n_in; i++) {
        if (in_sizes[i] == NROWS * NROWS) A = (const float*)d_in[i];
        else if (in_sizes[i] == FDIM * FDIM) W = (const float*)d_in[i];
        else if (in_sizes[i] == NROWS * FDIM) H = (const float*)d_in[i];
    }
    float* out = (float*)d_out;

    float* dptr = nullptr;
    __half* Ahp = nullptr;
    float* Qtp = nullptr;
    __half* Ptp = nullptr;
    cudaGetSymbolAddress((void**)&dptr, g_d);
    cudaGetSymbolAddress((void**)&Ahp, g_Ah);
    cudaGetSymbolAddress((void**)&Qtp, g_Qt);
    cudaGetSymbolAddress((void**)&Ptp, g_Pth);

    cudaFuncSetAttribute(spmm_mma, cudaFuncAttributeMaxDynamicSharedMemorySize, SMEM_BIG);

    // 1) fused: Qt = (H@W)^T fp32 (512 thin blocks, front)  ||  d, Ah
    fused_pre<<<GEMM_BLOCKS + NROWS, 256>>>(A, H, W, dptr, Ahp, Qtp);

    // 2) Pth = fp16(d[k] * Qt)
    scaleP<<<(FDIM * NROWS) / (256 * 8), 256>>>(Qtp, dptr, Ptp);

    // 3) out = relu(d_m * (Ah @ P)) -- 148 CTAs, KT=128/NS=3
    dim3 gridB(2, 74);
    spmm_mma<<<gridB, 256, SMEM_BIG>>>(Ahp, Ptp, dptr, out);
}